// round 1
// baseline (speedup 1.0000x reference)
#include <cuda_runtime.h>
#include <math.h>
#include <stdint.h>

// Problem constants
#define BB 2
#define TT 8192
#define CC 1024
#define HH 16
#define DD 64
#define MTOT (BB*TT)        // 16384
#define QKVC (3*CC)         // 3072

// Scratch (device globals: allocation-free per harness rules)
__device__ float g_qkv[(size_t)MTOT * QKVC];   // 192 MB: [B*T, 3072]
__device__ float g_scr[(size_t)MTOT * CC];     // 64 MB:  scrambled attn output [B*T2, 1024]
__device__ float g_cos[TT * 32];
__device__ float g_sin[TT * 32];

// ---------------------------------------------------------------------------
// RoPE table: cos/sin of fp32(t * fp32(10000^(-d2/32))) computed in double.
// Matches reference's fp32 freqs rounding, then near-correctly-rounded cos/sin.
// ---------------------------------------------------------------------------
__global__ void rope_table_kernel() {
    int idx = blockIdx.x * blockDim.x + threadIdx.x;
    if (idx >= TT * 32) return;
    int t  = idx >> 5;
    int d2 = idx & 31;
    float invf = (float)pow(10000.0, -(double)d2 / 32.0);
    float ang  = __fmul_rn((float)t, invf);      // fp32 product like the reference
    g_cos[idx] = (float)cos((double)ang);
    g_sin[idx] = (float)sin((double)ang);
}

// ---------------------------------------------------------------------------
// NT GEMM: C[m,n] = sum_k A[m,k] * B[n,k]. M,N multiples of 128, K mult of 8.
// 128x128 block tile, BK=8, 256 threads, 8x8 per-thread microtile. fp32 FFMA.
// ---------------------------------------------------------------------------
__global__ __launch_bounds__(256, 2) void gemm_nt_kernel(
    const float* __restrict__ A, const float* __restrict__ B,
    float* __restrict__ C, int N, int K)
{
    __shared__ float As[8][128];
    __shared__ float Bs[8][128];

    const int tid = threadIdx.x;
    const int m0 = blockIdx.y * 128;
    const int n0 = blockIdx.x * 128;

    const int lr = tid >> 1;            // 0..127 : row within tile
    const int lc = (tid & 1) << 2;      // 0 or 4 : starting col (float4)
    const float* Ag = A + (size_t)(m0 + lr) * K + lc;
    const float* Bg = B + (size_t)(n0 + lr) * K + lc;

    const int tx = tid & 15;
    const int ty = tid >> 4;

    float acc[8][8];
#pragma unroll
    for (int i = 0; i < 8; ++i)
#pragma unroll
        for (int j = 0; j < 8; ++j) acc[i][j] = 0.f;

    for (int k0 = 0; k0 < K; k0 += 8) {
        float4 av = *(const float4*)(Ag + k0);
        float4 bv = *(const float4*)(Bg + k0);
        __syncthreads();
        As[lc+0][lr] = av.x; As[lc+1][lr] = av.y; As[lc+2][lr] = av.z; As[lc+3][lr] = av.w;
        Bs[lc+0][lr] = bv.x; Bs[lc+1][lr] = bv.y; Bs[lc+2][lr] = bv.z; Bs[lc+3][lr] = bv.w;
        __syncthreads();
#pragma unroll
        for (int k = 0; k < 8; ++k) {
            float4 a0 = *(const float4*)&As[k][ty*4];
            float4 a1 = *(const float4*)&As[k][ty*4 + 64];
            float4 b0 = *(const float4*)&Bs[k][tx*4];
            float4 b1 = *(const float4*)&Bs[k][tx*4 + 64];
            float ar[8] = {a0.x,a0.y,a0.z,a0.w, a1.x,a1.y,a1.z,a1.w};
            float br[8] = {b0.x,b0.y,b0.z,b0.w, b1.x,b1.y,b1.z,b1.w};
#pragma unroll
            for (int i = 0; i < 8; ++i)
#pragma unroll
                for (int j = 0; j < 8; ++j)
                    acc[i][j] = fmaf(ar[i], br[j], acc[i][j]);
        }
    }

#pragma unroll
    for (int i = 0; i < 8; ++i) {
        int m = m0 + ty*4 + (i & 3) + (i >> 2) * 64;
        float4 c0 = make_float4(acc[i][0], acc[i][1], acc[i][2], acc[i][3]);
        float4 c1 = make_float4(acc[i][4], acc[i][5], acc[i][6], acc[i][7]);
        *(float4*)(C + (size_t)m * N + n0 + tx*4)      = c0;
        *(float4*)(C + (size_t)m * N + n0 + tx*4 + 64) = c1;
    }
}

// ---------------------------------------------------------------------------
// Fused RoPE + per-token 16x16 head-attention + scrambled scatter store.
// One block (256 threads) per token.
//   scr[b, h*512 + t/16, (t%16)*64 + d] = (softmax(q@k^T/8) @ v)[h, d]
// ---------------------------------------------------------------------------
#define PAD 65
__global__ __launch_bounds__(256) void attn_kernel()
{
    __shared__ float q [HH][PAD];
    __shared__ float kk[HH][PAD];
    __shared__ float vv[HH][PAD];
    __shared__ float sc[HH][17];
    __shared__ float cs[32], sn[32];

    const int tok = blockIdx.x;        // 0..16383
    const int b   = tok >> 13;
    const int t   = tok & (TT - 1);
    const int tid = threadIdx.x;

    if (tid < 32) { cs[tid] = g_cos[t*32 + tid]; sn[tid] = g_sin[t*32 + tid]; }

    // Load qkv row (3072 floats), coalesced
    const float* row = g_qkv + (size_t)tok * QKVC;
#pragma unroll
    for (int r = 0; r < 12; ++r) {
        int idx = tid + 256*r;
        float val = row[idx];
        int s = idx >> 10;            // 0=q, 1=k, 2=v
        int h = (idx >> 6) & 15;
        int d = idx & 63;
        if      (s == 0) q [h][d] = val;
        else if (s == 1) kk[h][d] = val;
        else             vv[h][d] = val;
    }
    __syncthreads();

    // RoPE on q and k: 2 tensors * 16 heads * 32 pairs = 1024 pair rotations
#pragma unroll
    for (int r = 0; r < 4; ++r) {
        int idx = tid + 256*r;        // 0..1023
        int which = idx >> 9;         // 0 -> q, 1 -> k
        int h  = (idx >> 5) & 15;
        int d2 = idx & 31;
        float c = cs[d2], s = sn[d2];
        float* buf = which ? &kk[0][0] : &q[0][0];
        float x1 = buf[h*PAD + 2*d2];
        float x2 = buf[h*PAD + 2*d2 + 1];
        buf[h*PAD + 2*d2]     = x1*c - x2*s;
        buf[h*PAD + 2*d2 + 1] = x2*c + x1*s;
    }
    __syncthreads();

    // Scores: 256 threads <-> 256 (hq,hk) pairs
    {
        int hq = tid >> 4, hk = tid & 15;
        float s = 0.f;
#pragma unroll
        for (int d = 0; d < DD; ++d) s = fmaf(q[hq][d], kk[hk][d], s);
        sc[hq][hk] = s * 0.125f;      // 1/sqrt(64)
    }
    __syncthreads();

    // Softmax over hk (rows), max-subtracted like jax.nn.softmax
    if (tid < 16) {
        float mx = -1e30f;
#pragma unroll
        for (int j = 0; j < 16; ++j) mx = fmaxf(mx, sc[tid][j]);
        float sum = 0.f;
#pragma unroll
        for (int j = 0; j < 16; ++j) { float e = expf(sc[tid][j] - mx); sc[tid][j] = e; sum += e; }
        float inv = 1.f / sum;
#pragma unroll
        for (int j = 0; j < 16; ++j) sc[tid][j] *= inv;
    }
    __syncthreads();

    // out[hq][d] = sum_hk attn[hq][hk] * v[hk][d]; scatter into scrambled layout
    const size_t obase = ((size_t)b * TT + (t >> 4)) * (size_t)CC + (size_t)(t & 15) * DD;
#pragma unroll
    for (int r = 0; r < 4; ++r) {
        int idx = tid + 256*r;        // 0..1023
        int hq = idx >> 6, d = idx & 63;
        float o = 0.f;
#pragma unroll
        for (int hk = 0; hk < 16; ++hk) o = fmaf(sc[hq][hk], vv[hk][d], o);
        g_scr[obase + (size_t)hq * 512 * CC + d] = o;
    }
}

// ---------------------------------------------------------------------------
extern "C" void kernel_launch(void* const* d_in, const int* in_sizes, int n_in,
                              void* d_out, int out_size)
{
    const float* x    = (const float*)d_in[0];   // [2, 8192, 1024]
    const float* Wqkv = (const float*)d_in[1];   // [3072, 1024]
    const float* Wout = (const float*)d_in[2];   // [1024, 1024]
    float* out = (float*)d_out;                  // [2, 8192, 1024]

    float *qkv_ptr = nullptr, *scr_ptr = nullptr;
    cudaGetSymbolAddress((void**)&qkv_ptr, g_qkv);
    cudaGetSymbolAddress((void**)&scr_ptr, g_scr);

    // 1) RoPE cos/sin table
    rope_table_kernel<<<(TT*32 + 255) / 256, 256>>>();

    // 2) GEMM1: qkv = x @ Wqkv^T   (M=16384, N=3072, K=1024)
    {
        dim3 grid(QKVC / 128, MTOT / 128);
        gemm_nt_kernel<<<grid, 256>>>(x, Wqkv, qkv_ptr, QKVC, CC);
    }

    // 3) Fused RoPE + head-attention + scramble
    attn_kernel<<<MTOT, 256>>>();

    // 4) GEMM2: out = scr @ Wout^T (M=16384, N=1024, K=1024)
    {
        dim3 grid(CC / 128, MTOT / 128);
        gemm_nt_kernel<<<grid, 256>>>(scr_ptr, Wout, out, CC, CC);
    }
}

// round 3
// speedup vs baseline: 2.1605x; 2.1605x over previous
#include <cuda_runtime.h>
#include <cuda_bf16.h>
#include <math.h>
#include <stdint.h>

#define BB 2
#define TT 8192
#define CC 1024
#define HH 16
#define DD 64
#define MTOT (BB*TT)        // 16384
#define QKVC (3*CC)         // 3072

// ---------------- device scratch ----------------
__device__ float g_qkv[(size_t)MTOT * QKVC];                 // 192 MB fp32
__device__ __nv_bfloat16 g_xh[(size_t)MTOT * CC];
__device__ __nv_bfloat16 g_xl[(size_t)MTOT * CC];
__device__ __nv_bfloat16 g_sh[(size_t)MTOT * CC];
__device__ __nv_bfloat16 g_sl[(size_t)MTOT * CC];
__device__ __nv_bfloat16 g_wqh[(size_t)QKVC * CC];
__device__ __nv_bfloat16 g_wql[(size_t)QKVC * CC];
__device__ __nv_bfloat16 g_woh[(size_t)CC * CC];
__device__ __nv_bfloat16 g_wol[(size_t)CC * CC];
__device__ float g_cos[TT * 32];
__device__ float g_sin[TT * 32];

// ---------------- PTX helpers (compute_103-baseline only) ----------------
__device__ __forceinline__ uint32_t smem_u32(const void* p) {
    uint32_t a;
    asm("{ .reg .u64 t; cvta.to.shared.u64 t, %1; cvt.u32.u64 %0, t; }" : "=r"(a) : "l"(p));
    return a;
}
__device__ __forceinline__ void cp16(uint32_t s, const void* g) {
    asm volatile("cp.async.cg.shared.global [%0], [%1], 16;" :: "r"(s), "l"(g));
}
#define CP_COMMIT() asm volatile("cp.async.commit_group;" ::: "memory")
#define CP_WAIT(n)  asm volatile("cp.async.wait_group %0;" :: "n"(n) : "memory")

__device__ __forceinline__ void ldsm_x4(uint32_t* r, uint32_t addr) {
    asm volatile("ldmatrix.sync.aligned.m8n8.x4.shared.b16 {%0,%1,%2,%3}, [%4];"
                 : "=r"(r[0]), "=r"(r[1]), "=r"(r[2]), "=r"(r[3]) : "r"(addr));
}
#define MMA_BF16(d, a, b0, b1) \
    asm volatile("mma.sync.aligned.m16n8k16.row.col.f32.bf16.bf16.f32 " \
                 "{%0,%1,%2,%3}, {%4,%5,%6,%7}, {%8,%9}, {%0,%1,%2,%3};" \
                 : "+f"((d)[0]), "+f"((d)[1]), "+f"((d)[2]), "+f"((d)[3]) \
                 : "r"((a)[0]), "r"((a)[1]), "r"((a)[2]), "r"((a)[3]), \
                   "r"(b0), "r"(b1))

// ---------------- small kernels ----------------
__global__ void rope_table_kernel() {
    int idx = blockIdx.x * blockDim.x + threadIdx.x;
    if (idx >= TT * 32) return;
    int t = idx >> 5, d2 = idx & 31;
    float invf = (float)pow(10000.0, -(double)d2 / 32.0);
    float ang = __fmul_rn((float)t, invf);
    g_cos[idx] = (float)cos((double)ang);
    g_sin[idx] = (float)sin((double)ang);
}

__global__ void split_kernel(const float4* __restrict__ in,
                             __nv_bfloat162* __restrict__ hi,
                             __nv_bfloat162* __restrict__ lo, int n4) {
    int i = blockIdx.x * blockDim.x + threadIdx.x;
    if (i >= n4) return;
    float4 v = in[i];
    __nv_bfloat16 h0 = __float2bfloat16(v.x), h1 = __float2bfloat16(v.y);
    __nv_bfloat16 h2 = __float2bfloat16(v.z), h3 = __float2bfloat16(v.w);
    __nv_bfloat162 H0; H0.x = h0; H0.y = h1;
    __nv_bfloat162 H1; H1.x = h2; H1.y = h3;
    __nv_bfloat162 L0; L0.x = __float2bfloat16(v.x - __bfloat162float(h0));
                       L0.y = __float2bfloat16(v.y - __bfloat162float(h1));
    __nv_bfloat162 L1; L1.x = __float2bfloat16(v.z - __bfloat162float(h2));
                       L1.y = __float2bfloat16(v.w - __bfloat162float(h3));
    hi[2*i] = H0; hi[2*i+1] = H1;
    lo[2*i] = L0; lo[2*i+1] = L1;
}

// ---------------- mma.sync GEMM (NT): C[m,n] = sum_k A[m,k]*B[n,k] ----------------
// bf16x3 split: Ah*Bh + Al*Bh + Ah*Bl, fp32 accum.
// 128x128 tile, BK=64, 3-stage cp.async pipeline, SW128 swizzle.
#define BM 128
#define BN 128
#define BKQ 64
#define T_AH 0
#define T_AL (16*1024)
#define T_BH (32*1024)
#define T_BL (48*1024)
#define STG  (64*1024)
#define NSTAGE 3
#define GEMM_DYN (NSTAGE*STG + 1024)

extern __shared__ char dynsmem[];

__global__ __launch_bounds__(256, 1) void gemm_mma(
    const __nv_bfloat16* __restrict__ Ah, const __nv_bfloat16* __restrict__ Al,
    const __nv_bfloat16* __restrict__ Bh, const __nv_bfloat16* __restrict__ Bl,
    float* __restrict__ C, int ldc, int K)
{
    const int tid  = threadIdx.x;
    const int wid  = tid >> 5;
    const int lane = tid & 31;
    const int m0 = blockIdx.y * BM;
    const int n0 = blockIdx.x * BN;
    const int wm = (wid >> 1) * 32;   // warp m offset in tile
    const int wn = (wid & 1) * 64;    // warp n offset in tile

    uint32_t sbase = (smem_u32(dynsmem) + 1023u) & ~1023u;

    // ---- loader setup: each thread loads row tid/2, 4x16B chunks per tensor ----
    const int lrow = tid >> 1;
    const int lc4  = (tid & 1) * 4;   // first 16B chunk index (of 8 per 128B row)
    uint32_t soff[4];
#pragma unroll
    for (int c = 0; c < 4; ++c) {
        uint32_t off = (uint32_t)lrow * 128 + (uint32_t)(lc4 + c) * 16;
        soff[c] = off ^ ((off >> 3) & 0x70);
    }
    const __nv_bfloat16* gAh = Ah + (size_t)(m0 + lrow) * K + lc4 * 8;
    const __nv_bfloat16* gAl = Al + (size_t)(m0 + lrow) * K + lc4 * 8;
    const __nv_bfloat16* gBh = Bh + (size_t)(n0 + lrow) * K + lc4 * 8;
    const __nv_bfloat16* gBl = Bl + (size_t)(n0 + lrow) * K + lc4 * 8;

    auto load_stage = [&](int stage, int iter) {
        uint32_t st = sbase + (uint32_t)stage * STG;
        const int k0 = iter * BKQ;
#pragma unroll
        for (int c = 0; c < 4; ++c) {
            cp16(st + T_AH + soff[c], gAh + k0 + c * 8);
            cp16(st + T_AL + soff[c], gAl + k0 + c * 8);
            cp16(st + T_BH + soff[c], gBh + k0 + c * 8);
            cp16(st + T_BL + soff[c], gBl + k0 + c * 8);
        }
        CP_COMMIT();
    };

    // ---- ldmatrix address precompute ----
    // A 16x16 tile at (wm+ti*16, ks*16): lanes 0-15 rows, lanes 16-31 rows w/ +16B col
    uint32_t a_rt[2], a_xr[2];
#pragma unroll
    for (int ti = 0; ti < 2; ++ti) {
        int r = wm + ti * 16 + (lane & 15);
        a_rt[ti] = (uint32_t)r * 128;
        a_xr[ti] = (uint32_t)(r & 7) << 4;
    }
    const uint32_t a_cb = (uint32_t)(lane >> 4) * 16;
    // B 16x16 tile at (wn+ni*16, ks*16): mats (n0-7,k0-7),(n0-7,k8-15),(n8-15,k0-7),(n8-15,k8-15)
    uint32_t b_rt[4], b_xr[4];
#pragma unroll
    for (int ni = 0; ni < 4; ++ni) {
        int r = wn + ni * 16 + (lane & 7) + (lane >> 4) * 8;
        b_rt[ni] = (uint32_t)r * 128;
        b_xr[ni] = (uint32_t)(r & 7) << 4;
    }
    const uint32_t b_cb = (uint32_t)((lane >> 3) & 1) * 16;

    float acc[2][8][4];
#pragma unroll
    for (int i = 0; i < 2; ++i)
#pragma unroll
        for (int j = 0; j < 8; ++j)
#pragma unroll
            for (int q = 0; q < 4; ++q) acc[i][j][q] = 0.f;

    const int niter = K / BKQ;   // 16

    // prologue: fill NSTAGE-1 stages
#pragma unroll
    for (int s = 0; s < NSTAGE - 1; ++s) load_stage(s, s);

    for (int i = 0; i < niter; ++i) {
        if (i + NSTAGE - 1 < niter) { CP_WAIT(1); } else { CP_WAIT(0); }
        __syncthreads();
        if (i + NSTAGE - 1 < niter) load_stage((i + NSTAGE - 1) % NSTAGE, i + NSTAGE - 1);

        uint32_t base = sbase + (uint32_t)(i % NSTAGE) * STG;
#pragma unroll
        for (int ks = 0; ks < 4; ++ks) {
            const uint32_t kb = (uint32_t)ks * 32;
            uint32_t ah[2][4], al[2][4], bh[4][4], bl[4][4];
#pragma unroll
            for (int ti = 0; ti < 2; ++ti) {
                uint32_t col = (a_cb + kb) ^ a_xr[ti];
                ldsm_x4(ah[ti], base + T_AH + a_rt[ti] + col);
                ldsm_x4(al[ti], base + T_AL + a_rt[ti] + col);
            }
#pragma unroll
            for (int ni = 0; ni < 4; ++ni) {
                uint32_t col = (b_cb + kb) ^ b_xr[ni];
                ldsm_x4(bh[ni], base + T_BH + b_rt[ni] + col);
                ldsm_x4(bl[ni], base + T_BL + b_rt[ni] + col);
            }
#pragma unroll
            for (int mi = 0; mi < 2; ++mi)
#pragma unroll
                for (int ni = 0; ni < 4; ++ni) {
                    MMA_BF16(acc[mi][2*ni],   ah[mi], bh[ni][0], bh[ni][1]);
                    MMA_BF16(acc[mi][2*ni],   al[mi], bh[ni][0], bh[ni][1]);
                    MMA_BF16(acc[mi][2*ni],   ah[mi], bl[ni][0], bl[ni][1]);
                    MMA_BF16(acc[mi][2*ni+1], ah[mi], bh[ni][2], bh[ni][3]);
                    MMA_BF16(acc[mi][2*ni+1], al[mi], bh[ni][2], bh[ni][3]);
                    MMA_BF16(acc[mi][2*ni+1], ah[mi], bl[ni][2], bl[ni][3]);
                }
        }
        __syncthreads();
    }

    // ---- epilogue: registers -> global fp32 ----
#pragma unroll
    for (int mi = 0; mi < 2; ++mi) {
        int gm = m0 + wm + mi * 16 + (lane >> 2);
#pragma unroll
        for (int ni = 0; ni < 8; ++ni) {
            int gn = n0 + wn + ni * 8 + (lane & 3) * 2;
            float2 v0 = make_float2(acc[mi][ni][0], acc[mi][ni][1]);
            float2 v1 = make_float2(acc[mi][ni][2], acc[mi][ni][3]);
            *(float2*)(C + (size_t)gm * ldc + gn) = v0;
            *(float2*)(C + (size_t)(gm + 8) * ldc + gn) = v1;
        }
    }
}

// ---------------- fused RoPE + per-token 16x16 head-attn + scrambled bf16 split ----------------
#define PAD 65
__global__ __launch_bounds__(256) void attn_kernel()
{
    __shared__ float q [HH][PAD];
    __shared__ float kk[HH][PAD];
    __shared__ float vv[HH][PAD];
    __shared__ float sc[HH][17];
    __shared__ float cs[32], sn[32];

    const int tok = blockIdx.x;
    const int b = tok >> 13;
    const int t = tok & (TT - 1);
    const int tid = threadIdx.x;

    if (tid < 32) { cs[tid] = g_cos[t*32 + tid]; sn[tid] = g_sin[t*32 + tid]; }

    const float* row = g_qkv + (size_t)tok * QKVC;
#pragma unroll
    for (int r = 0; r < 12; ++r) {
        int idx = tid + 256 * r;
        float val = row[idx];
        int s = idx >> 10;
        int h = (idx >> 6) & 15;
        int d = idx & 63;
        if      (s == 0) q [h][d] = val;
        else if (s == 1) kk[h][d] = val;
        else             vv[h][d] = val;
    }
    __syncthreads();

#pragma unroll
    for (int r = 0; r < 4; ++r) {
        int idx = tid + 256 * r;
        int which = idx >> 9;
        int h = (idx >> 5) & 15;
        int d2 = idx & 31;
        float c = cs[d2], s = sn[d2];
        float* buf = which ? &kk[0][0] : &q[0][0];
        float x1 = buf[h*PAD + 2*d2];
        float x2 = buf[h*PAD + 2*d2 + 1];
        buf[h*PAD + 2*d2]     = x1*c - x2*s;
        buf[h*PAD + 2*d2 + 1] = x2*c + x1*s;
    }
    __syncthreads();

    {
        int hq = tid >> 4, hk = tid & 15;
        float s = 0.f;
#pragma unroll
        for (int d = 0; d < DD; ++d) s = fmaf(q[hq][d], kk[hk][d], s);
        sc[hq][hk] = s * 0.125f;
    }
    __syncthreads();

    if (tid < 16) {
        float mx = -1e30f;
#pragma unroll
        for (int j = 0; j < 16; ++j) mx = fmaxf(mx, sc[tid][j]);
        float sum = 0.f;
#pragma unroll
        for (int j = 0; j < 16; ++j) { float e = expf(sc[tid][j] - mx); sc[tid][j] = e; sum += e; }
        float inv = 1.f / sum;
#pragma unroll
        for (int j = 0; j < 16; ++j) sc[tid][j] *= inv;
    }
    __syncthreads();

    const size_t obase = ((size_t)b * TT + (t >> 4)) * (size_t)CC + (size_t)(t & 15) * DD;
#pragma unroll
    for (int r = 0; r < 4; ++r) {
        int idx = tid + 256 * r;
        int hq = idx >> 6, d = idx & 63;
        float o = 0.f;
#pragma unroll
        for (int hk = 0; hk < 16; ++hk) o = fmaf(sc[hq][hk], vv[hk][d], o);
        size_t oi = obase + (size_t)hq * 512 * CC + d;
        __nv_bfloat16 h = __float2bfloat16(o);
        g_sh[oi] = h;
        g_sl[oi] = __float2bfloat16(o - __bfloat162float(h));
    }
}

// ---------------------------------------------------------------------------
extern "C" void kernel_launch(void* const* d_in, const int* in_sizes, int n_in,
                              void* d_out, int out_size)
{
    const float* x    = (const float*)d_in[0];
    const float* Wqkv = (const float*)d_in[1];
    const float* Wout = (const float*)d_in[2];
    float* out = (float*)d_out;

    float *qkv_p;
    __nv_bfloat16 *xh, *xl, *sh, *sl, *wqh, *wql, *woh, *wol;
    cudaGetSymbolAddress((void**)&qkv_p, g_qkv);
    cudaGetSymbolAddress((void**)&xh, g_xh);   cudaGetSymbolAddress((void**)&xl, g_xl);
    cudaGetSymbolAddress((void**)&sh, g_sh);   cudaGetSymbolAddress((void**)&sl, g_sl);
    cudaGetSymbolAddress((void**)&wqh, g_wqh); cudaGetSymbolAddress((void**)&wql, g_wql);
    cudaGetSymbolAddress((void**)&woh, g_woh); cudaGetSymbolAddress((void**)&wol, g_wol);

    cudaFuncSetAttribute(gemm_mma, cudaFuncAttributeMaxDynamicSharedMemorySize, GEMM_DYN);

    rope_table_kernel<<<(TT*32 + 255) / 256, 256>>>();
    split_kernel<<<(MTOT*CC/4 + 255) / 256, 256>>>((const float4*)x,    (__nv_bfloat162*)xh,  (__nv_bfloat162*)xl,  MTOT*CC/4);
    split_kernel<<<(QKVC*CC/4 + 255) / 256, 256>>>((const float4*)Wqkv, (__nv_bfloat162*)wqh, (__nv_bfloat162*)wql, QKVC*CC/4);
    split_kernel<<<(CC*CC/4   + 255) / 256, 256>>>((const float4*)Wout, (__nv_bfloat162*)woh, (__nv_bfloat162*)wol, CC*CC/4);

    // GEMM1: qkv = x @ Wqkv^T  (M=16384, N=3072, K=1024)
    {
        dim3 grid(QKVC / BN, MTOT / BM);
        gemm_mma<<<grid, 256, GEMM_DYN>>>(xh, xl, wqh, wql, qkv_p, QKVC, CC);
    }

    // fused RoPE + head-attention + scramble + bf16 split
    attn_kernel<<<MTOT, 256>>>();

    // GEMM2: out = scr @ Wout^T (M=16384, N=1024, K=1024)
    {
        dim3 grid(CC / BN, MTOT / BM);
        gemm_mma<<<grid, 256, GEMM_DYN>>>(sh, sl, woh, wol, out, CC, CC);
    }
}